// round 17
// baseline (speedup 1.0000x reference)
#include <cuda_runtime.h>
#include <cstdint>

#define GRID1   20
#define NCPAD   8192
#define CAP     16             // bucket capacity (overflow P ~ 2e-12)
#define KC      20             // merged candidate cap (P(cnt>20) ~ 1e-9)
#define KC_L    12             // per-quad-thread local cap
#define STAGE   24             // per-row smem staging slots
#define CSTRIDE 32
#define MAXM    8192
#define MAXN    8192
#define GBLK    128
#define TBLK    256
#define GSZ     4              // threads per pred row (round-13/15 optimum)
#define ROWS_PB (TBLK / GSZ)   // 64 rows per block

typedef unsigned long long u64;
#define OWNER_INIT (~0ull)

// ---------------- device scratch (no allocations allowed) ----------------
__device__ int            g_cellcnt[NCPAD];          // zero-init; finalize re-zeros
__device__ float4         g_bucketA[NCPAD * CAP];    // (x,y,z,bitcast id)
__device__ float4         g_bucketB[NCPAD * CAP];    // (l,w,h,yaw)
__device__ uint4          g_row[MAXM];               // cnt | first 7 sorted candidates
__device__ unsigned short g_sorted[MAXM * CSTRIDE];  // overflow (pos >= 7)
__device__ float          g_candL[MAXM * CSTRIDE];   // per-candidate pair loss
__device__ u64            g_owner[MAXN];             // ((row<<5|pos)<<32) | fbits(L)
__device__ float          g_accN;                    // loss numerator (telescoped)
__device__ float          g_accK;                    // match count
__device__ volatile unsigned g_bcnt[4];              // zero-init; self-resetting
__device__ volatile unsigned g_bgen[4];              // monotonic generation

__device__ __forceinline__ int cell1(float x) {
    int c = (int)floorf(x * 0.2f);
    return min(max(c, 0), GRID1 - 1);
}

// Generation-based grid barrier; all GBLK blocks co-resident (128 <= 148 SMs).
__device__ __forceinline__ void gsync(int k) {
    __syncthreads();
    if (threadIdx.x == 0) {
        unsigned old = g_bgen[k];
        __threadfence();
        unsigned a = atomicAdd((unsigned*)&g_bcnt[k], 1u);
        if (a == GBLK - 1) {
            g_bcnt[k] = 0;
            __threadfence();
            atomicAdd((unsigned*)&g_bgen[k], 1u);
        } else {
            while (g_bgen[k] == old) { }
        }
    }
    __syncthreads();
    __threadfence();
}

// candidate p of a row given its packed uint4; own=true may use L1 (own writes)
__device__ __forceinline__ int cand_at(uint4 rv, int p, int row, bool own) {
    if (p < 7) {
        unsigned w = (p == 0) ? rv.x : (p < 3) ? rv.y : (p < 5) ? rv.z : rv.w;
        int sh = (p == 0) ? 16 : ((p & 1) ? 0 : 16);
        return (int)((w >> sh) & 0xFFFFu);
    }
    const unsigned short* q = &g_sorted[(size_t)row * CSTRIDE + p];
    return own ? (int)*q : (int)__ldcg(q);
}

__device__ __forceinline__ float sl1(float x) {
    float a = fabsf(x);
    return (a < 1.0f) ? 0.5f * a * a : a - 0.5f;
}

// Per-pair loss numerator from register-resident rows (computed ONCE, in B).
__device__ __forceinline__ float pair_numer(const float* P, const float* G) {
    float sc = sl1(P[0] - G[0]) + sl1(P[1] - G[1]) + sl1(P[2] - G[2]);
    float ss = sl1(P[3] - G[3]) + sl1(P[4] - G[4]) + sl1(P[5] - G[5]);
    float dth = P[6] - G[6];
    dth = fmaf(-rintf(dth * 0.15915494309f), 6.283185307f, dth);
    float so = sl1(dth);                 // sl1(|.|) symmetric: wrap dir irrelevant
    float iw = fminf(P[0] + P[3] * 0.5f, G[0] + G[3] * 0.5f)
             - fmaxf(P[0] - P[3] * 0.5f, G[0] - G[3] * 0.5f);
    iw = fmaxf(iw, 0.0f);
    float ih = fminf(P[1] + P[4] * 0.5f, G[1] + G[4] * 0.5f)
             - fmaxf(P[1] - P[4] * 0.5f, G[1] - G[4] * 0.5f);
    ih = fmaxf(ih, 0.0f);
    float inter = iw * ih;
    float uni = P[3] * P[4] + G[3] * G[4] - inter;
    float si = 1.0f - inter / (uni + 1e-6f);
    return sc * (1.0f / 3.0f) + 0.5f * (ss * (1.0f / 3.0f) + so) + 2.0f * si;
}

__global__ void __launch_bounds__(TBLK)
fused_kernel(const float* __restrict__ pred, const float* __restrict__ gt,
             int m, int n, float* __restrict__ out) {
    __shared__ u64   s_keys[ROWS_PB * STAGE];   // 12 KB staging
    __shared__ float s_Lv[ROWS_PB * STAGE];     // 6 KB paired losses
    __shared__ int   s_cnt[ROWS_PB];
    int b = blockIdx.x, tid = threadIdx.x;
    int gtid = b * TBLK + tid;
    int row  = gtid >> 2;                        // quad: 4 threads per pred row
    int q    = tid & (GSZ - 1);
    int lrow = tid >> 2;                         // row index within block
    bool rowv = (row < m);
    bool lead = (q == 0) && rowv;

    if (tid < ROWS_PB) s_cnt[tid] = 0;

    // All quad lanes load their row's FULL pred row (2 sectors; broadcast).
    float P[7] = {0, 0, 0, 0, 0, 0, 0};
    if (rowv) {
        #pragma unroll
        for (int k = 0; k < 7; ++k) P[k] = __ldg(&pred[(size_t)row * 7 + k]);
    }

    // ========== phase A: build + init, spread over ALL 128 blocks ==========
    if (b == 0 && tid == ROWS_PB)     g_accN = 0.0f;
    if (b == 0 && tid == ROWS_PB + 1) g_accK = 0.0f;
    if (tid < ROWS_PB) {
        int r = b * ROWS_PB + tid;
        if (r < n) {
            g_owner[r] = OWNER_INIT;
            const float* g = gt + (size_t)r * 7;
            float g0 = __ldg(g),     g1 = __ldg(g + 1), g2 = __ldg(g + 2);
            float g3 = __ldg(g + 3), g4 = __ldg(g + 4), g5 = __ldg(g + 5);
            float g6 = __ldg(g + 6);
            int c = (cell1(g2) * GRID1 + cell1(g1)) * GRID1 + cell1(g0);
            int slot = atomicAdd(&g_cellcnt[c], 1);
            if (slot < CAP) {
                g_bucketA[c * CAP + slot] =
                    make_float4(g0, g1, g2, __int_as_float(r));
                g_bucketB[c * CAP + slot] = make_float4(g3, g4, g5, g6);
            }
        }
    }
    gsync(0);

    // ========== phase B: quad-parallel query + AT-HIT loss =================
    // 27 neighbor cells split 7-per-quad-thread (k = q + 4t, k<27): union ==
    // full [cell1(px-5),cell1(px+5)]^3 superset (monotone f32 ops); exact
    // dsq<25 test -> identical candidate set to brute force (rounds 1-16).
    // Keys (fbits(dsq)<<32 | j) unique; paired (key, L) min-sweep preserves
    // the exact serial-argmin key order. L computed here, once, from
    // register-resident P and G — phase C never touches pred/gt again.
    uint4 rv = make_uint4(0, 0, 0, 0);
    int   cnt = 0;
    if (rowv) {
        float px = P[0], py = P[1], pz = P[2];
        int x0 = cell1(px - 5.0f), x1 = cell1(px + 5.0f);
        int y0 = cell1(py - 5.0f), y1 = cell1(py + 5.0f);
        int z0 = cell1(pz - 5.0f), z1 = cell1(pz + 5.0f);

        u64   lk[KC_L];
        float lL[KC_L];
        #pragma unroll
        for (int k = 0; k < KC_L; ++k) { lk[k] = ~0ull; lL[k] = 0.0f; }
        int lc = 0;

        int    cc[7], ci[7];
        float4 vA[7], vB[7];
        #pragma unroll
        for (int t = 0; t < 7; ++t) {
            int k = q + GSZ * t;
            int zz = z0 + k / 9, yy = y0 + (k % 9) / 3, xx = x0 + k % 3;
            bool ok = (k < 27) && (zz <= z1) && (yy <= y1) && (xx <= x1);
            int c = (zz * GRID1 + yy) * GRID1 + xx;
            c = min(max(c, 0), NCPAD - 1);       // clamp: always in-bounds
            ci[t] = c;
            cc[t] = ok ? __ldg(&g_cellcnt[c]) : 0;
        }
        #pragma unroll
        for (int t = 0; t < 7; ++t) vA[t] = __ldg(&g_bucketA[ci[t] * CAP]);
        #pragma unroll
        for (int t = 0; t < 7; ++t) vB[t] = __ldg(&g_bucketB[ci[t] * CAP]);

        #pragma unroll
        for (int t = 0; t < 7; ++t) {
            int c2 = min(cc[t], CAP);
            for (int e = 0; e < c2; ++e) {       // c2>1 rare (mean ~1)
                float4 a4 = (e == 0) ? vA[t] : __ldg(&g_bucketA[ci[t] * CAP + e]);
                float4 b4 = (e == 0) ? vB[t] : __ldg(&g_bucketB[ci[t] * CAP + e]);
                float dx = px - a4.x, dy = py - a4.y, dz = pz - a4.z;
                float d = fmaf(dx, dx, fmaf(dy, dy, dz * dz));
                if (d < 25.0f) {
                    u64 key = ((u64)__float_as_uint(d) << 32)
                            | (unsigned)__float_as_int(a4.w);
                    float G[7] = {a4.x, a4.y, a4.z, b4.x, b4.y, b4.z, b4.w};
                    float L = pair_numer(P, G);
                    ++lc;
                    #pragma unroll
                    for (int k2 = 0; k2 < KC_L; ++k2) {   // paired min-sweep
                        bool sw = key < lk[k2];
                        u64 tk = lk[k2];  float tL = lL[k2];
                        lk[k2] = sw ? key : tk;  lL[k2] = sw ? L : tL;
                        key    = sw ? tk : key;  L      = sw ? tL : L;
                    }
                }
            }
        }
        lc = min(lc, KC_L);
        if (lc > 0) {
            int pos = atomicAdd(&s_cnt[lrow], lc);
            #pragma unroll
            for (int e = 0; e < KC_L; ++e)
                if (e < lc && pos + e < STAGE) {
                    s_keys[lrow * STAGE + pos + e] = lk[e];
                    s_Lv[lrow * STAGE + pos + e]   = lL[e];
                }
        }
    }
    __syncwarp(0xFFFFFFFFu);                     // quad is intra-warp

    if (lead) {
        int tot = min(s_cnt[lrow], STAGE);
        unsigned c7[7];
        if (tot <= 8) {
            // fast path (P ~ 97%): 8-wide paired min-sweep merge
            u64   a8[8];
            float l8[8];
            #pragma unroll
            for (int k = 0; k < 8; ++k) { a8[k] = ~0ull; l8[k] = 0.0f; }
            for (int e = 0; e < tot; ++e) {
                u64   key = s_keys[lrow * STAGE + e];
                float L   = s_Lv[lrow * STAGE + e];
                #pragma unroll
                for (int k2 = 0; k2 < 8; ++k2) {
                    bool sw = key < a8[k2];
                    u64 tk = a8[k2];  float tL = l8[k2];
                    a8[k2] = sw ? key : tk;  l8[k2] = sw ? L : tL;
                    key    = sw ? tk : key;  L      = sw ? tL : L;
                }
            }
            cnt = tot;
            #pragma unroll
            for (int k = 0; k < 7; ++k)
                c7[k] = (k < cnt) ? (unsigned)(a8[k] & 0xFFFFu) : 0u;
            if (cnt == 8)
                g_sorted[(size_t)row * CSTRIDE + 7] =
                    (unsigned short)(a8[7] & 0xFFFFu);
            #pragma unroll
            for (int k = 0; k < 8; ++k)
                if (k < cnt) g_candL[(size_t)row * CSTRIDE + k] = l8[k];
        } else {
            // rare path: local-mem insertion sort on (key, L) pairs
            u64   ls[STAGE];
            float lf[STAGE];
            for (int e = 0; e < tot; ++e) {
                ls[e] = s_keys[lrow * STAGE + e];
                lf[e] = s_Lv[lrow * STAGE + e];
            }
            for (int e = 1; e < tot; ++e) {
                u64 v = ls[e];  float Lf = lf[e];
                int d = e;
                while (d > 0 && ls[d - 1] > v) {
                    ls[d] = ls[d - 1]; lf[d] = lf[d - 1]; --d;
                }
                ls[d] = v;  lf[d] = Lf;
            }
            cnt = min(tot, KC);
            #pragma unroll
            for (int k = 0; k < 7; ++k)
                c7[k] = (k < cnt) ? (unsigned)(ls[k] & 0xFFFFu) : 0u;
            for (int k = 7; k < cnt; ++k)
                g_sorted[(size_t)row * CSTRIDE + k] =
                    (unsigned short)(ls[k] & 0xFFFFu);
            for (int k = 0; k < cnt; ++k)
                g_candL[(size_t)row * CSTRIDE + k] = lf[k];
        }
        rv.x = (unsigned)cnt | (c7[0] << 16);
        rv.y = c7[1] | (c7[2] << 16);
        rv.z = c7[3] | (c7[4] << 16);
        rv.w = c7[5] | (c7[6] << 16);
        g_row[row] = rv;
    }
    __threadfence();   // release g_row/g_sorted/g_candL before owner atomics

    // ========== phase C: eager-chain matcher, lean links ===================
    // owner64[j] = min of ((row<<5|pos)<<32 | fbits(L)). High bits: verified
    // packed priority (unique) -> atomicMin ordering identical to rounds
    // 8-16; L rides in low bits. Telescoped accounting per linearized owner
    // transition (INIT->v: +L,K+1; v->v': +L'-L_old from the word). L always
    // comes from g_candL (single source) -> exact telescoping. Links touch
    // NO pred/gt data: g_row ldcg -> (candL + peek, one wave) -> atomicMin.
    // Peek-skip safe by monotonicity (current <= stale < mine).
    if (lead) {
        int cur = row, p = 0, ccnt = cnt;
        uint4 crv = rv;
        bool own = true;
        while (p < ccnt) {
            int j = cand_at(crv, p, cur, own);
            const float* lp = &g_candL[(size_t)cur * CSTRIDE + p];
            float L = own ? *lp : __ldcg(lp);
            u64 peek = __ldcg(&g_owner[j]);      // same wave as L
            u64 myhi = (u64)((unsigned)((cur << 5) | p));
            if ((peek >> 32) < myhi) { ++p; continue; }   // hopeless: skip
            u64 my = (myhi << 32) | (u64)__float_as_uint(L);
            u64 old = atomicMin(&g_owner[j], my);
            if (old < my) { ++p; continue; }              // lost race: advance
            if (old == OWNER_INIT) {                      // claimed empty slot
                atomicAdd(&g_accN, L);
                atomicAdd(&g_accK, 1.0f);
                break;
            }
            // displaced previous owner: swap contribution, continue its walk
            float Lold = __uint_as_float((unsigned)(old & 0xFFFFFFFFull));
            atomicAdd(&g_accN, L - Lold);
            cur = (int)(old >> 37);
            p = (int)((old >> 32) & 31u) + 1;
            crv = __ldcg(&g_row[cur]);
            ccnt = (int)(crv.x & 0xFFFFu);
            own = false;
        }
    }

    // ========== finalize: arrive-only; last block writes out + cleanup =====
    __syncthreads();
    __shared__ int s_last;
    if (tid == 0) {
        __threadfence();                 // order this block's REDs
        unsigned a = atomicAdd((unsigned*)&g_bcnt[2], 1u);
        s_last = (a == GBLK - 1) ? 1 : 0;
        if (s_last) g_bcnt[2] = 0;
    }
    __syncthreads();
    if (s_last) {
        if (tid == 0) {
            float N = atomicAdd(&g_accN, 0.0f);
            float K = atomicAdd(&g_accK, 0.0f);
            out[0] = N / fmaxf(K, 1.0f);
        }
        for (int c = tid; c < NCPAD; c += TBLK)   // zero-state for next replay
            g_cellcnt[c] = 0;
    }
}

// ---------------- launch ----------------
extern "C" void kernel_launch(void* const* d_in, const int* in_sizes, int n_in,
                              void* d_out, int out_size) {
    const float* pred = (const float*)d_in[0];
    const float* gt   = (const float*)d_in[1];
    int m = in_sizes[0] / 7;
    int n = in_sizes[1] / 7;
    fused_kernel<<<GBLK, TBLK>>>(pred, gt, m, n, (float*)d_out);
}